// round 14
// baseline (speedup 1.0000x reference)
#include <cuda_runtime.h>
#include <cuda_fp16.h>
#include <cstdint>

// Problem constants
#define N_FEAT  65536
#define N_PROTO 512
#define DIMK    256

#define BLK_M   256                 // feature rows per CTA
#define BLK_N   64                  // protos per chunk
#define N_CHUNKS 8

// SMEM layout (bytes)
#define SM_FSQ   0                          // 256 floats
#define SM_PSQ   1024                       // 512 floats
#define SM_A     4096                       // 16 mtiles * 16 ksteps * 512 B = 131072
#define SM_B0    (SM_A + 131072)            // buf: 4 pair-slabs * 16 s * 512 B = 32768
#define SM_B1    (SM_B0 + 32768)
#define SMEM_TOTAL (SM_B1 + 32768)          // 200704 B

// pack float2 -> fp16x2 (x -> low half)
__device__ __forceinline__ uint32_t pk(float2 f) {
    __half2 h = __floats2half2_rn(f.x, f.y);
    return *(uint32_t*)&h;
}

// m16n8k16 fp16 MMA, fp32 accumulate
__device__ __forceinline__ void mma_f16(float d[4], const uint32_t a[4],
                                        uint32_t b0, uint32_t b1) {
    asm volatile(
        "mma.sync.aligned.m16n8k16.row.col.f32.f16.f16.f32 "
        "{%0,%1,%2,%3}, {%4,%5,%6,%7}, {%8,%9}, {%0,%1,%2,%3};"
        : "+f"(d[0]), "+f"(d[1]), "+f"(d[2]), "+f"(d[3])
        : "r"(a[0]), "r"(a[1]), "r"(a[2]), "r"(a[3]),
          "r"(b0), "r"(b1));
}

// ---------------------------------------------------------------------------
// R13 skeleton (pipelined stores, dual acc sets) with fatter N tile:
//   A slab (mtile t, kstep s): 32 lanes x uint4 = 512 B           (as before)
//   B PAIR slab (pair p, kstep s): 32 lanes x uint4 = 512 B,
//     uint4 = {b0(u=2p), b1(u=2p), b0(u=2p+1), b1(u=2p+1)}
// Mainloop k-step per warp: 3 x LDS.128 feeding 8 MMAs (T=2 x U=4).
// Warp grid 8(M) x 2(N). Stores of chunk c-1 interleave into chunk c.
// ---------------------------------------------------------------------------
__global__ void __launch_bounds__(512, 1) proto_dist_kernel(
    const float* __restrict__ feat,
    const float* __restrict__ proto,
    float* __restrict__ out1,    // [N, P]
    float* __restrict__ out2)    // [P, N]
{
    extern __shared__ char smem[];
    float* s_fsq = (float*)(smem + SM_FSQ);
    float* s_psq = (float*)(smem + SM_PSQ);

    const int tid  = threadIdx.x;
    const int lane = tid & 31;
    const int wid  = tid >> 5;     // 0..15
    const int g    = lane >> 2;
    const int tig  = lane & 3;
    const int m0   = blockIdx.x * BLK_M;

    const int mi   = wid >> 1;     // 0..7 — M position (T=2 -> 32 rows)
    const int nj   = wid & 1;      // 0..1 — N position (U=4 -> 32 protos)

    // ---- Stage A tile (256 x 256) as fp16 fragments + exact fp32 feat norms ----
    {
        const int t = wid;                       // warp w stages mtile w
        const float* rA = feat + (size_t)(m0 + t * 16 + g) * DIMK;
        const float* rB = rA + 8 * DIMK;
        float sqA = 0.f, sqB = 0.f;
#pragma unroll
        for (int s = 0; s < 16; s++) {
            const int kA = s * 16 + 2 * tig;
            float2 f0 = *(const float2*)(rA + kA);
            float2 f1 = *(const float2*)(rB + kA);
            float2 f2 = *(const float2*)(rA + kA + 8);
            float2 f3 = *(const float2*)(rB + kA + 8);
            sqA += f0.x * f0.x + f0.y * f0.y + f2.x * f2.x + f2.y * f2.y;
            sqB += f1.x * f1.x + f1.y * f1.y + f3.x * f3.x + f3.y * f3.y;
            uint4 w;
            w.x = pk(f0); w.y = pk(f1); w.z = pk(f2); w.w = pk(f3);
            *(uint4*)(smem + SM_A + (size_t)((t * 16 + s) * 32 + lane) * 16) = w;
        }
        sqA += __shfl_xor_sync(0xffffffffu, sqA, 1);
        sqA += __shfl_xor_sync(0xffffffffu, sqA, 2);
        sqB += __shfl_xor_sync(0xffffffffu, sqB, 1);
        sqB += __shfl_xor_sync(0xffffffffu, sqB, 2);
        if (tig == 0) {
            s_fsq[t * 16 + g]     = sqA;
            s_fsq[t * 16 + g + 8] = sqB;
        }
    }

    // ---- All 512 prototype norms, exact fp32 (proto is L2-hot: 512 KB) ----
    {
        const float4* r = (const float4*)(proto + (size_t)tid * DIMK);
        float s0 = 0.f, s1 = 0.f, s2 = 0.f, s3 = 0.f;
#pragma unroll
        for (int j = 0; j < 64; j += 4) {
            float4 v0 = r[j], v1 = r[j + 1], v2 = r[j + 2], v3 = r[j + 3];
            s0 += v0.x * v0.x + v0.y * v0.y + v0.z * v0.z + v0.w * v0.w;
            s1 += v1.x * v1.x + v1.y * v1.y + v1.z * v1.z + v1.w * v1.w;
            s2 += v2.x * v2.x + v2.y * v2.y + v2.z * v2.z + v2.w * v2.w;
            s3 += v3.x * v3.x + v3.y * v3.y + v3.z * v3.z + v3.w * v3.w;
        }
        s_psq[tid] = (s0 + s1) + (s2 + s3);
    }

    // ---- B staging: 64 protos = 8 ntiles; warp w stages ntile u=w>>1,
    //      kstep half h=w&1. Pair p=u>>1, inner offset (u&1)*8. ----
    const int su = wid >> 1, sh = wid & 1;
    auto stage_B = [&](int c, char* buf) {
        const float* r = proto + (size_t)(c * BLK_N + su * 8 + g) * DIMK;
        char* dst = buf + (su >> 1) * 8192 + (su & 1) * 8 + (size_t)lane * 16;
#pragma unroll
        for (int j = 0; j < 8; j++) {
            const int s  = sh * 8 + j;
            const int kA = s * 16 + 2 * tig;
            float2 f0 = *(const float2*)(r + kA);
            float2 f1 = *(const float2*)(r + kA + 8);
            uint2 w;
            w.x = pk(f0); w.y = pk(f1);
            *(uint2*)(dst + (size_t)s * 512) = w;
        }
    };

    stage_B(0, smem + SM_B0);
    __syncthreads();   // A frags + norms + B(chunk 0) visible

    // Per-warp epilogue constants
    const char* baseA = smem + SM_A + (size_t)((mi * 2) * 16) * 512 + (size_t)lane * 16;
    float fsr[2][2];
    float* row1[2][2];
    int   mcol[2][2];
#pragma unroll
    for (int tp = 0; tp < 2; tp++) {
#pragma unroll
        for (int h = 0; h < 2; h++) {
            const int ml = mi * 32 + tp * 16 + h * 8 + g;
            fsr[tp][h]  = s_fsq[ml];
            row1[tp][h] = out1 + (size_t)(m0 + ml) * N_PROTO;
            mcol[tp][h] = m0 + ml;
        }
    }
    const int plbase = nj * 32 + 2 * tig;   // + up*8

    float accA[2][4][4], accB[2][4][4];

    // compute accC from bufC; store pend (chunk at proto offset p0p) if has_pend
    auto run_chunk = [&](float (&accC)[2][4][4], float (&pend)[2][4][4],
                         const char* bufC, bool has_pend, int p0p) {
#pragma unroll
        for (int tp = 0; tp < 2; tp++)
#pragma unroll
            for (int up = 0; up < 4; up++)
#pragma unroll
                for (int e = 0; e < 4; e++) accC[tp][up][e] = 0.f;

        if (has_pend) {
            // transform pending accumulators into distances, in place
#pragma unroll
            for (int q = 0; q < 8; q++) {
                const int tp = q >> 2, up = q & 3;
                const int pl = plbase + up * 8;
                const float2 ps = *(const float2*)(s_psq + p0p + pl);
                float* d = pend[tp][up];
                d[0] = fsr[tp][0] + ps.x - 2.0f * d[0];
                d[1] = fsr[tp][0] + ps.y - 2.0f * d[1];
                d[2] = fsr[tp][1] + ps.x - 2.0f * d[2];
                d[3] = fsr[tp][1] + ps.y - 2.0f * d[3];
            }
        }

        const char* bB = bufC + (nj * 2) * 8192 + (size_t)lane * 16;

#pragma unroll
        for (int s = 0; s < 16; s++) {
            uint4 a[2];
#pragma unroll
            for (int tp = 0; tp < 2; tp++)
                a[tp] = *(const uint4*)(baseA + (size_t)(tp * 16 + s) * 512);
            const uint4 b01 = *(const uint4*)(bB + (size_t)s * 512);
            const uint4 b23 = *(const uint4*)(bB + 8192 + (size_t)s * 512);
#pragma unroll
            for (int tp = 0; tp < 2; tp++) {
                mma_f16(accC[tp][0], (const uint32_t*)&a[tp], b01.x, b01.y);
                mma_f16(accC[tp][1], (const uint32_t*)&a[tp], b01.z, b01.w);
                mma_f16(accC[tp][2], (const uint32_t*)&a[tp], b23.x, b23.y);
                mma_f16(accC[tp][3], (const uint32_t*)&a[tp], b23.z, b23.w);
            }

            // interleave pending stores: 16 phases, q = s>>1, jj = s&1
            if (has_pend) {
                const int q  = s >> 1;
                const int tp = q >> 2, up = q & 3;
                const int pl = plbase + up * 8;
                const float* d = pend[tp][up];
                if ((s & 1) == 0) {
                    // out1 [N,P]: full 32B sector per 4-lane quad
                    *(float2*)(row1[tp][0] + p0p + pl) = make_float2(d[0], d[1]);
                    *(float2*)(row1[tp][1] + p0p + pl) = make_float2(d[2], d[3]);
                } else {
                    // out2 [P,N]: 8 g-lanes = full 32B sector per column
                    out2[(size_t)(p0p + pl)     * N_FEAT + mcol[tp][0]] = d[0];
                    out2[(size_t)(p0p + pl + 1) * N_FEAT + mcol[tp][0]] = d[1];
                    out2[(size_t)(p0p + pl)     * N_FEAT + mcol[tp][1]] = d[2];
                    out2[(size_t)(p0p + pl + 1) * N_FEAT + mcol[tp][1]] = d[3];
                }
            }
        }
    };

    for (int c2 = 0; c2 < N_CHUNKS / 2; c2++) {
        const int cA = 2 * c2, cB = 2 * c2 + 1;
        // phase A: compute chunk cA (buf0); store chunk cA-1 (accB)
        stage_B(cB, smem + SM_B1);
        run_chunk(accA, accB, smem + SM_B0, c2 > 0, (cA - 1) * BLK_N);
        __syncthreads();   // buf1 ready; buf0 consumed
        // phase B: compute chunk cB (buf1); store chunk cA (accA)
        if (cB + 1 < N_CHUNKS) stage_B(cB + 1, smem + SM_B0);
        run_chunk(accB, accA, smem + SM_B1, true, cA * BLK_N);
        __syncthreads();   // buf0 ready; buf1 consumed
    }

    // ---- tail: store chunk N_CHUNKS-1 from accB ----
    {
        const int p0p = (N_CHUNKS - 1) * BLK_N;
#pragma unroll
        for (int q = 0; q < 8; q++) {
            const int tp = q >> 2, up = q & 3;
            const int pl = plbase + up * 8;
            const float2 ps = *(const float2*)(s_psq + p0p + pl);
            float* d = accB[tp][up];
            d[0] = fsr[tp][0] + ps.x - 2.0f * d[0];
            d[1] = fsr[tp][0] + ps.y - 2.0f * d[1];
            d[2] = fsr[tp][1] + ps.x - 2.0f * d[2];
            d[3] = fsr[tp][1] + ps.y - 2.0f * d[3];
            *(float2*)(row1[tp][0] + p0p + pl) = make_float2(d[0], d[1]);
            *(float2*)(row1[tp][1] + p0p + pl) = make_float2(d[2], d[3]);
            out2[(size_t)(p0p + pl)     * N_FEAT + mcol[tp][0]] = d[0];
            out2[(size_t)(p0p + pl + 1) * N_FEAT + mcol[tp][0]] = d[1];
            out2[(size_t)(p0p + pl)     * N_FEAT + mcol[tp][1]] = d[2];
            out2[(size_t)(p0p + pl + 1) * N_FEAT + mcol[tp][1]] = d[3];
        }
    }
}

// ---------------------------------------------------------------------------
// Launch
// ---------------------------------------------------------------------------
extern "C" void kernel_launch(void* const* d_in, const int* in_sizes, int n_in,
                              void* d_out, int out_size)
{
    (void)in_sizes; (void)n_in; (void)out_size;
    const float* feat  = (const float*)d_in[0];
    const float* proto = (const float*)d_in[1];
    float* out1 = (float*)d_out;
    float* out2 = out1 + (size_t)N_FEAT * N_PROTO;

    cudaFuncSetAttribute(proto_dist_kernel,
                         cudaFuncAttributeMaxDynamicSharedMemorySize, SMEM_TOTAL);

    proto_dist_kernel<<<N_FEAT / BLK_M, 512, SMEM_TOTAL>>>(feat, proto, out1, out2);
}